// round 15
// baseline (speedup 1.0000x reference)
#include <cuda_runtime.h>
#include <math.h>

// Swin stage: B=4, H=W=256, C=96, NH=6, HD=16, WS=8, N=64; 4096 windows.
// bf16 m16n8k16 everywhere + ldmatrix fragment loads + LDG.128 weights.
// V transposed on the fly via ldmatrix.x2.trans (no f32 V plane, no transpose pass).

#define W_WORDS   110592

__device__ unsigned g_w[W_WORDS];    // packed bf16x2 weights

#define OFF_QKV0   0
#define OFF_QKV1   13824
#define OFF_PROJ0  27648
#define OFF_PROJ1  32256
#define OFF_F1_0   36864
#define OFF_F1_1   55296
#define OFF_F2_0   73728
#define OFF_F2_1   92160

__device__ __forceinline__ unsigned pack_bf16x2(float lo, float hi) {
    unsigned r; asm("cvt.rn.bf16x2.f32 %0, %1, %2;" : "=r"(r) : "f"(hi), "f"(lo));
    return r;
}
__device__ __forceinline__ void mma_bf16(float* c, const unsigned* a, const unsigned* b) {
    asm volatile(
        "mma.sync.aligned.m16n8k16.row.col.f32.bf16.bf16.f32 "
        "{%0,%1,%2,%3},{%4,%5,%6,%7},{%8,%9},{%0,%1,%2,%3};\n"
        : "+f"(c[0]), "+f"(c[1]), "+f"(c[2]), "+f"(c[3])
        : "r"(a[0]), "r"(a[1]), "r"(a[2]), "r"(a[3]), "r"(b[0]), "r"(b[1]));
}
__device__ __forceinline__ unsigned sptr(const void* p) {
    unsigned a;
    asm("{ .reg .u64 t; cvta.to.shared.u64 t, %1; cvt.u32.u64 %0, t; }"
        : "=r"(a) : "l"(p));
    return a;
}
__device__ __forceinline__ void ldsm_x4(unsigned* r, unsigned saddr) {
    asm volatile("ldmatrix.sync.aligned.m8n8.x4.shared.b16 {%0,%1,%2,%3}, [%4];"
        : "=r"(r[0]), "=r"(r[1]), "=r"(r[2]), "=r"(r[3]) : "r"(saddr));
}
__device__ __forceinline__ void ldsm_x2(unsigned* r, unsigned saddr) {
    asm volatile("ldmatrix.sync.aligned.m8n8.x2.shared.b16 {%0,%1}, [%2];"
        : "=r"(r[0]), "=r"(r[1]) : "r"(saddr));
}
__device__ __forceinline__ void ldsm_x2t(unsigned* r, unsigned saddr) {
    asm volatile("ldmatrix.sync.aligned.m8n8.x2.trans.shared.b16 {%0,%1}, [%2];"
        : "=r"(r[0]), "=r"(r[1]) : "r"(saddr));
}

// ---- bf16 weight packer: per-thread k-tiles contiguous (uint4-loadable) ----
// word index within region: ((ntg*32 + lane)*KS16 + kk)*2 + j
__global__ void pack_all(const float* __restrict__ qkvw, const float* __restrict__ projw,
                         const float* __restrict__ f1w,  const float* __restrict__ f2w,
                         unsigned* __restrict__ dst) {
    int idx = blockIdx.x * 256 + threadIdx.x;
    if (idx >= W_WORDS) return;
    const float* src; int K, local;
    if (idx < 27648)      { int r = idx;          src = qkvw  + (r/13824)*27648; K=96;  local = r % 13824; }
    else if (idx < 36864) { int r = idx - 27648;  src = projw + (r/4608)*9216;   K=96;  local = r % 4608; }
    else if (idx < 73728) { int r = idx - 36864;  src = f1w   + (r/18432)*36864; K=96;  local = r % 18432; }
    else                  { int r = idx - 73728;  src = f2w   + (r/18432)*36864; K=384; local = r % 18432; }
    int j    = local & 1;
    int r1   = local >> 1;
    int KS16 = K >> 4;
    int kk   = r1 % KS16;
    int r2   = r1 / KS16;
    int lane = r2 & 31;
    int ntg  = r2 >> 5;
    int n  = ntg * 8 + (lane >> 2);
    int k0 = kk * 16 + j * 8 + 2 * (lane & 3);
    dst[idx] = pack_bf16x2(src[n * K + k0], src[n * K + k0 + 1]);
}

#define SWZ_T(c, t) ((c) ^ (((t) & 7) << 2))

// ======================= attention kernel =======================
// smem words: xsw[64][52]=3328 | qkv[64][148]=9472 (q w0-47, k w48-95, v w96-143)
//   | sc f32 [64][64]=4096 (XOR) | probw[64][36]=2304    total 19200 w = 76800 B
#define XSW_OFF   0
#define QKW_OFF   3328
#define SC_OFF    12800
#define PROBW_OFF 16896
#define ATTN_SMEM_WORDS 19200
#define QP 148

__global__ void __launch_bounds__(256, 2) attn_kernel(
    const float* __restrict__ xin, float* __restrict__ xout,
    const unsigned* __restrict__ wqkv, const float* __restrict__ qkvb,
    const unsigned* __restrict__ wproj, const float* __restrict__ projb,
    const float* __restrict__ rpb,
    const float* __restrict__ g1, const float* __restrict__ bb1,
    int shift)
{
    extern __shared__ float sm[];
    unsigned* xsw   = (unsigned*)sm + XSW_OFF;
    unsigned* qkw   = (unsigned*)sm + QKW_OFF;
    float*    sc    = sm + SC_OFF;
    unsigned* probw = (unsigned*)sm + PROBW_OFF;

    const int tid = threadIdx.x, lane = tid & 31, wid = tid >> 5;
    const int g = lane >> 2, tg = lane & 3;
    const int wm = wid >> 1, wn = wid & 1;
    const int m0 = wm * 16;
    const int l15 = lane & 15, sel4 = (lane >> 4) << 2;

    const int win = blockIdx.x;
    const int b = win >> 10, wi = win & 1023, wh = wi >> 5, ww = wi & 31;

    // ---------- phase 1: LN1 -> xsw (bf16x2) ----------
    {
        int t = tid >> 2, l4 = tid & 3;
        int th = t >> 3, tw = t & 7;
        int h0 = (wh*8 + th + shift) & 255, w0 = (ww*8 + tw + shift) & 255;
        const float* xr = xin + ((size_t)b*65536 + (size_t)h0*256 + w0)*96;
        float v0[12], v1[12], s = 0.f, ss = 0.f;
        #pragma unroll
        for (int jw = 0; jw < 12; jw++) {
            float2 p = *(const float2*)&xr[2*(l4 + 4*jw)];
            v0[jw] = p.x; v1[jw] = p.y;
            s += p.x + p.y; ss += p.x*p.x + p.y*p.y;
        }
        s  += __shfl_xor_sync(0xffffffffu, s, 1);
        s  += __shfl_xor_sync(0xffffffffu, s, 2);
        ss += __shfl_xor_sync(0xffffffffu, ss, 1);
        ss += __shfl_xor_sync(0xffffffffu, ss, 2);
        float mean = s * (1.f/96.f);
        float rstd = rsqrtf(ss * (1.f/96.f) - mean*mean + 1e-5f);
        #pragma unroll
        for (int jw = 0; jw < 12; jw++) {
            int w = l4 + 4*jw;
            int c0 = 2*w;
            float a = (v0[jw]-mean)*rstd*g1[c0]   + bb1[c0];
            float b2 = (v1[jw]-mean)*rstd*g1[c0+1] + bb1[c0+1];
            xsw[t*52 + w] = pack_bf16x2(a, b2);
        }
    }
    __syncthreads();

    // ---------- phase 2: QKV GEMM (bf16); q/k/v -> qkw packed along d ----------
    {
        unsigned Af[6][4];
        #pragma unroll
        for (int kk = 0; kk < 6; kk++)
            ldsm_x4(Af[kk], sptr(&xsw[(m0 + l15)*52 + kk*8 + sel4]));
        for (int s3 = 0; s3 < 3; s3++) {
            float acc[6][4];
            #pragma unroll
            for (int i = 0; i < 6; i++) { acc[i][0]=acc[i][1]=acc[i][2]=acc[i][3]=0.f; }
            #pragma unroll
            for (int kk = 0; kk < 6; kk += 2) {
                #pragma unroll
                for (int nt = 0; nt < 6; nt++) {
                    int ntg = s3*12 + wn*6 + nt;
                    uint4 wv = *(const uint4*)&wqkv[((ntg*32 + lane)*6 + kk)*2];
                    unsigned b0[2] = { wv.x, wv.y };
                    unsigned b1[2] = { wv.z, wv.w };
                    mma_bf16(acc[nt], Af[kk],   b0);
                    mma_bf16(acc[nt], Af[kk+1], b1);
                }
            }
            #pragma unroll
            for (int nt = 0; nt < 6; nt++) {
                #pragma unroll
                for (int i = 0; i < 2; i++) {
                    int ncol = wn*48 + nt*8 + 2*tg;
                    int m = m0 + g + i*8;
                    float a = acc[nt][i*2]   + __ldg(&qkvb[s3*96 + ncol]);
                    float c2 = acc[nt][i*2+1] + __ldg(&qkvb[s3*96 + ncol + 1]);
                    if (s3 == 0) { a *= 0.25f; c2 *= 0.25f; }
                    int w = s3*48 + wn*24 + nt*4 + tg;
                    qkw[m*QP + w] = pack_bf16x2(a, c2);
                }
            }
        }
    }
    __syncthreads();

    // ---------- phase 3: per-head attention (bf16 core) ----------
    for (int h = 0; h < 6; h++) {
        // scores: warp tile [m0,m0+16) x [wn*32,+32)
        {
            unsigned Aq[4];
            ldsm_x4(Aq, sptr(&qkw[(m0 + l15)*QP + h*8 + sel4]));
            float acc[4][4];
            #pragma unroll
            for (int i = 0; i < 4; i++) { acc[i][0]=acc[i][1]=acc[i][2]=acc[i][3]=0.f; }
            #pragma unroll
            for (int nt = 0; nt < 4; nt++) {
                int u0 = wn*32 + nt*8;
                unsigned Bk[2];
                ldsm_x2(Bk, sptr(&qkw[(u0 + (lane & 7))*QP + 48 + h*8 + (((lane>>3)&1)<<2)]));
                mma_bf16(acc[nt], Aq, Bk);
            }
            #pragma unroll
            for (int nt = 0; nt < 4; nt++) {
                #pragma unroll
                for (int i = 0; i < 2; i++) {
                    #pragma unroll
                    for (int j = 0; j < 2; j++) {
                        int t = m0 + g + i*8;
                        int u = wn*32 + nt*8 + 2*tg + j;
                        int ti = t>>3, tj = t&7, ui = u>>3, uj = u&7;
                        float d = acc[nt][i*2+j]
                                + __ldg(&rpb[((ti-ui+7)*15 + (tj-uj+7))*6 + h]);
                        if (shift) {
                            int hrt = wh*8+ti, wrt = ww*8+tj;
                            int hru = wh*8+ui, wru = ww*8+uj;
                            int rt = (hrt<248?0:(hrt<252?1:2))*3 + (wrt<248?0:(wrt<252?1:2));
                            int ru = (hru<248?0:(hru<252?1:2))*3 + (wru<248?0:(wru<252?1:2));
                            if (rt != ru) d -= 100.f;
                        }
                        sc[t*64 + SWZ_T(u, t)] = d;
                    }
                }
            }
        }
        __syncthreads();

        // softmax (f32) -> probw (bf16x2 along u)
        {
            int t = tid >> 2, l4 = tid & 3;
            float e0[8], e1[8];
            float mx = -1e30f;
            #pragma unroll
            for (int jw = 0; jw < 8; jw++) {
                int a = SWZ_T(2*(l4 + 4*jw), t);
                float2 p = *(const float2*)&sc[t*64 + a];
                e0[jw] = p.x; e1[jw] = p.y;
                mx = fmaxf(mx, fmaxf(p.x, p.y));
            }
            mx = fmaxf(mx, __shfl_xor_sync(0xffffffffu, mx, 1));
            mx = fmaxf(mx, __shfl_xor_sync(0xffffffffu, mx, 2));
            float sum = 0.f;
            #pragma unroll
            for (int jw = 0; jw < 8; jw++) {
                e0[jw] = __expf(e0[jw] - mx);
                e1[jw] = __expf(e1[jw] - mx);
                sum += e0[jw] + e1[jw];
            }
            sum += __shfl_xor_sync(0xffffffffu, sum, 1);
            sum += __shfl_xor_sync(0xffffffffu, sum, 2);
            float inv = 1.f / sum;
            #pragma unroll
            for (int jw = 0; jw < 8; jw++)
                probw[t*36 + l4 + 4*jw] = pack_bf16x2(e0[jw]*inv, e1[jw]*inv);
        }
        __syncthreads();

        // P@V (bf16): V B-frags transposed on the fly
        {
            float av[4] = {0.f, 0.f, 0.f, 0.f};
            int dw = 96 + h*8 + wn*4;          // v d-word base for this head/wn
            #pragma unroll
            for (int kk = 0; kk < 4; kk++) {
                unsigned Ap[4];
                ldsm_x4(Ap, sptr(&probw[(m0 + l15)*36 + kk*8 + sel4]));
                unsigned Bv[2];
                ldsm_x2t(Bv, sptr(&qkw[(kk*16 + l15)*QP + dw]));
                mma_bf16(av, Ap, Bv);
            }
            int wv = h*8 + wn*4 + tg;
            xsw[(m0+g)*52   + wv] = pack_bf16x2(av[0], av[1]);
            xsw[(m0+g+8)*52 + wv] = pack_bf16x2(av[2], av[3]);
        }
        __syncthreads();
    }

    // ---------- phase 4: proj (bf16) + residual -> gmem ----------
    {
        unsigned Ac[6][4];
        #pragma unroll
        for (int kk = 0; kk < 6; kk++)
            ldsm_x4(Ac[kk], sptr(&xsw[(m0 + l15)*52 + kk*8 + sel4]));
        float acc[6][4];
        #pragma unroll
        for (int i = 0; i < 6; i++) { acc[i][0]=acc[i][1]=acc[i][2]=acc[i][3]=0.f; }
        #pragma unroll
        for (int kk = 0; kk < 6; kk += 2) {
            #pragma unroll
            for (int nt = 0; nt < 6; nt++) {
                int ntg = wn*6 + nt;
                uint4 wv = *(const uint4*)&wproj[((ntg*32 + lane)*6 + kk)*2];
                unsigned b0[2] = { wv.x, wv.y };
                unsigned b1[2] = { wv.z, wv.w };
                mma_bf16(acc[nt], Ac[kk],   b0);
                mma_bf16(acc[nt], Ac[kk+1], b1);
            }
        }
        #pragma unroll
        for (int nt = 0; nt < 6; nt++) {
            #pragma unroll
            for (int i = 0; i < 2; i++) {
                int ncol0 = wn*48 + nt*8 + 2*tg;
                int m = m0 + g + i*8;
                int th = m >> 3, tw = m & 7;
                int h0 = (wh*8 + th + shift) & 255;
                int w0 = (ww*8 + tw + shift) & 255;
                size_t row = ((size_t)b*65536 + (size_t)h0*256 + w0)*96;
                float2 rr = *(const float2*)&xin[row + ncol0];
                float2 o;
                o.x = rr.x + acc[nt][i*2]   + __ldg(&projb[ncol0]);
                o.y = rr.y + acc[nt][i*2+1] + __ldg(&projb[ncol0+1]);
                *(float2*)&xout[row + ncol0] = o;
            }
        }
    }
}

// ======================= MLP kernel =======================
#define MLP_SMEM_WORDS (3328 + 3328)

__global__ void __launch_bounds__(256, 2) mlp_kernel(
    const float* __restrict__ xin, float* __restrict__ xout,
    const float* __restrict__ g2, const float* __restrict__ bb2,
    const unsigned* __restrict__ w1p, const float* __restrict__ b1v,
    const unsigned* __restrict__ w2p, const float* __restrict__ b2v)
{
    extern __shared__ float sm[];
    unsigned* xsw = (unsigned*)sm;
    unsigned* ybw = (unsigned*)sm + 3328;

    const int tid = threadIdx.x, lane = tid & 31, wid = tid >> 5;
    const int g = lane >> 2, tg = lane & 3;
    const int wm = wid >> 1, wn = wid & 1;
    const int m0 = wm * 16;
    const int l15 = lane & 15, sel4 = (lane >> 4) << 2;
    const size_t base = (size_t)blockIdx.x * 64 * 96;

    {
        int t = tid >> 2, l4 = tid & 3;
        const float* xr = xin + base + (size_t)t*96;
        float v0[12], v1[12], s = 0.f, ss = 0.f;
        #pragma unroll
        for (int jw = 0; jw < 12; jw++) {
            float2 p = *(const float2*)&xr[2*(l4 + 4*jw)];
            v0[jw] = p.x; v1[jw] = p.y;
            s += p.x + p.y; ss += p.x*p.x + p.y*p.y;
        }
        s  += __shfl_xor_sync(0xffffffffu, s, 1);
        s  += __shfl_xor_sync(0xffffffffu, s, 2);
        ss += __shfl_xor_sync(0xffffffffu, ss, 1);
        ss += __shfl_xor_sync(0xffffffffu, ss, 2);
        float mean = s * (1.f/96.f);
        float rstd = rsqrtf(ss * (1.f/96.f) - mean*mean + 1e-5f);
        #pragma unroll
        for (int jw = 0; jw < 12; jw++) {
            int w = l4 + 4*jw;
            int c0 = 2*w;
            float a = (v0[jw]-mean)*rstd*g2[c0]   + bb2[c0];
            float b2 = (v1[jw]-mean)*rstd*g2[c0+1] + bb2[c0+1];
            xsw[t*52 + w] = pack_bf16x2(a, b2);
        }
    }
    __syncthreads();

    unsigned Af[6][4];
    #pragma unroll
    for (int kk = 0; kk < 6; kk++)
        ldsm_x4(Af[kk], sptr(&xsw[(m0 + l15)*52 + kk*8 + sel4]));

    float acc2[6][4];
    #pragma unroll
    for (int i = 0; i < 6; i++) { acc2[i][0]=acc2[i][1]=acc2[i][2]=acc2[i][3]=0.f; }

    for (int ch = 0; ch < 4; ch++) {
        float acc[6][4];
        #pragma unroll
        for (int i = 0; i < 6; i++) { acc[i][0]=acc[i][1]=acc[i][2]=acc[i][3]=0.f; }
        #pragma unroll
        for (int kk = 0; kk < 6; kk += 2) {
            #pragma unroll
            for (int nt = 0; nt < 6; nt++) {
                int ntg = ch*12 + wn*6 + nt;
                uint4 wv = *(const uint4*)&w1p[((ntg*32 + lane)*6 + kk)*2];
                unsigned b0[2] = { wv.x, wv.y };
                unsigned b1[2] = { wv.z, wv.w };
                mma_bf16(acc[nt], Af[kk],   b0);
                mma_bf16(acc[nt], Af[kk+1], b1);
            }
        }
        #pragma unroll
        for (int nt = 0; nt < 6; nt++) {
            int wv = wn*24 + nt*4 + tg;
            #pragma unroll
            for (int i = 0; i < 2; i++) {
                int c0 = wn*48 + nt*8 + 2*tg;
                float a = acc[nt][i*2]   + __ldg(&b1v[ch*96 + c0]);
                float b2 = acc[nt][i*2+1] + __ldg(&b1v[ch*96 + c0 + 1]);
                a = a * normcdff(a);
                b2 = b2 * normcdff(b2);
                ybw[(m0+g+i*8)*52 + wv] = pack_bf16x2(a, b2);
            }
        }
        __syncthreads();
        #pragma unroll
        for (int kk = 0; kk < 6; kk += 2) {
            unsigned Ay0[4], Ay1[4];
            ldsm_x4(Ay0, sptr(&ybw[(m0 + l15)*52 + kk*8 + sel4]));
            ldsm_x4(Ay1, sptr(&ybw[(m0 + l15)*52 + (kk+1)*8 + sel4]));
            #pragma unroll
            for (int nt = 0; nt < 6; nt++) {
                int ntg = wn*6 + nt;
                int kkg = ch*6 + kk;
                uint4 wv = *(const uint4*)&w2p[((ntg*32 + lane)*24 + kkg)*2];
                unsigned b0[2] = { wv.x, wv.y };
                unsigned b1[2] = { wv.z, wv.w };
                mma_bf16(acc2[nt], Ay0, b0);
                mma_bf16(acc2[nt], Ay1, b1);
            }
        }
        __syncthreads();
    }

    #pragma unroll
    for (int nt = 0; nt < 6; nt++) {
        #pragma unroll
        for (int i = 0; i < 2; i++) {
            int c0 = wn*48 + nt*8 + 2*tg;
            int m = m0 + g + i*8;
            float2 r = *(const float2*)&xin[base + (size_t)m*96 + c0];
            float2 o;
            o.x = r.x + acc2[nt][i*2]   + __ldg(&b2v[c0]);
            o.y = r.y + acc2[nt][i*2+1] + __ldg(&b2v[c0+1]);
            *(float2*)&xout[base + (size_t)m*96 + c0] = o;
        }
    }
}

// ======================= launcher =======================
extern "C" void kernel_launch(void* const* d_in, const int* in_sizes, int n_in,
                              void* d_out, int out_size) {
    const float* x    = (const float*)d_in[0];
    const float* qkvw = (const float*)d_in[1];
    const float* qkvb = (const float*)d_in[2];
    const float* projw= (const float*)d_in[3];
    const float* projb= (const float*)d_in[4];
    const float* rpb  = (const float*)d_in[5];
    const float* n1w  = (const float*)d_in[6];
    const float* n1b  = (const float*)d_in[7];
    const float* n2w  = (const float*)d_in[8];
    const float* n2b  = (const float*)d_in[9];
    const float* f1w  = (const float*)d_in[10];
    const float* f1b  = (const float*)d_in[11];
    const float* f2w  = (const float*)d_in[12];
    const float* f2b  = (const float*)d_in[13];
    float* out = (float*)d_out;

    unsigned* gw = nullptr;  cudaGetSymbolAddress((void**)&gw, g_w);

    pack_all<<<(W_WORDS + 255)/256, 256>>>(qkvw, projw, f1w, f2w, gw);

    const int ATTN_SMEM = ATTN_SMEM_WORDS * 4;   // 76800 B -> 2 CTAs/SM
    const int MLP_SMEM  = MLP_SMEM_WORDS * 4;    // 26624 B
    cudaFuncSetAttribute(attn_kernel, cudaFuncAttributeMaxDynamicSharedMemorySize, ATTN_SMEM);
    cudaFuncSetAttribute(mlp_kernel,  cudaFuncAttributeMaxDynamicSharedMemorySize, MLP_SMEM);

    const int NBLK = 4096;

    attn_kernel<<<NBLK, 256, ATTN_SMEM>>>(x, out,
        gw + OFF_QKV0, qkvb, gw + OFF_PROJ0, projb, rpb, n1w, n1b, 0);
    mlp_kernel<<<NBLK, 256, MLP_SMEM>>>(out, out,
        n2w, n2b, gw + OFF_F1_0, f1b, gw + OFF_F2_0, f2b);

    attn_kernel<<<NBLK, 256, ATTN_SMEM>>>(out, out,
        gw + OFF_QKV1, qkvb + 288, gw + OFF_PROJ1, projb + 96,
        rpb + 225*6, n1w + 96, n1b + 96, 4);
    mlp_kernel<<<NBLK, 256, MLP_SMEM>>>(out, out,
        n2w + 96, n2b + 96, gw + OFF_F1_1, f1b + 384, gw + OFF_F2_1, f2b + 96);
}

// round 16
// speedup vs baseline: 1.3046x; 1.3046x over previous
#include <cuda_runtime.h>
#include <math.h>

// Swin stage: B=4, H=W=256, C=96, NH=6, HD=16, WS=8, N=64; 4096 windows.
// bf16 m16n8k16 everywhere + ldmatrix fragment loads.
// Weights: lane-major packed (coalesced uint2 loads) — R15's thread-major
// LDG.128 layout was uncoalesced and regressed; reverted.
// V transposed on the fly via ldmatrix.x2.trans (no f32 V plane).

#define W_WORDS   110592

__device__ unsigned g_w[W_WORDS];    // packed bf16x2 weights

#define OFF_QKV0   0
#define OFF_QKV1   13824
#define OFF_PROJ0  27648
#define OFF_PROJ1  32256
#define OFF_F1_0   36864
#define OFF_F1_1   55296
#define OFF_F2_0   73728
#define OFF_F2_1   92160

__device__ __forceinline__ unsigned pack_bf16x2(float lo, float hi) {
    unsigned r; asm("cvt.rn.bf16x2.f32 %0, %1, %2;" : "=r"(r) : "f"(hi), "f"(lo));
    return r;
}
__device__ __forceinline__ void mma_bf16(float* c, const unsigned* a, const unsigned* b) {
    asm volatile(
        "mma.sync.aligned.m16n8k16.row.col.f32.bf16.bf16.f32 "
        "{%0,%1,%2,%3},{%4,%5,%6,%7},{%8,%9},{%0,%1,%2,%3};\n"
        : "+f"(c[0]), "+f"(c[1]), "+f"(c[2]), "+f"(c[3])
        : "r"(a[0]), "r"(a[1]), "r"(a[2]), "r"(a[3]), "r"(b[0]), "r"(b[1]));
}
__device__ __forceinline__ unsigned sptr(const void* p) {
    unsigned a;
    asm("{ .reg .u64 t; cvta.to.shared.u64 t, %1; cvt.u32.u64 %0, t; }"
        : "=r"(a) : "l"(p));
    return a;
}
__device__ __forceinline__ void ldsm_x4(unsigned* r, unsigned saddr) {
    asm volatile("ldmatrix.sync.aligned.m8n8.x4.shared.b16 {%0,%1,%2,%3}, [%4];"
        : "=r"(r[0]), "=r"(r[1]), "=r"(r[2]), "=r"(r[3]) : "r"(saddr));
}
__device__ __forceinline__ void ldsm_x2(unsigned* r, unsigned saddr) {
    asm volatile("ldmatrix.sync.aligned.m8n8.x2.shared.b16 {%0,%1}, [%2];"
        : "=r"(r[0]), "=r"(r[1]) : "r"(saddr));
}
__device__ __forceinline__ void ldsm_x2t(unsigned* r, unsigned saddr) {
    asm volatile("ldmatrix.sync.aligned.m8n8.x2.trans.shared.b16 {%0,%1}, [%2];"
        : "=r"(r[0]), "=r"(r[1]) : "r"(saddr));
}

// ---- bf16 weight packer: LANE-MAJOR (coalesced) ----
// word index within region: ((ntg*KS16 + kk)*32 + lane)*2 + j
__global__ void pack_all(const float* __restrict__ qkvw, const float* __restrict__ projw,
                         const float* __restrict__ f1w,  const float* __restrict__ f2w,
                         unsigned* __restrict__ dst) {
    int idx = blockIdx.x * 256 + threadIdx.x;
    if (idx >= W_WORDS) return;
    const float* src; int K, local;
    if (idx < 27648)      { int r = idx;          src = qkvw  + (r/13824)*27648; K=96;  local = r % 13824; }
    else if (idx < 36864) { int r = idx - 27648;  src = projw + (r/4608)*9216;   K=96;  local = r % 4608; }
    else if (idx < 73728) { int r = idx - 36864;  src = f1w   + (r/18432)*36864; K=96;  local = r % 18432; }
    else                  { int r = idx - 73728;  src = f2w   + (r/18432)*36864; K=384; local = r % 18432; }
    int j    = local & 1;
    int lane = (local >> 1) & 31;
    int rest = local >> 6;
    int KS16 = K >> 4;
    int kk   = rest % KS16;
    int ntg  = rest / KS16;
    int n  = ntg * 8 + (lane >> 2);
    int k0 = kk * 16 + j * 8 + 2 * (lane & 3);
    dst[idx] = pack_bf16x2(src[n * K + k0], src[n * K + k0 + 1]);
}

#define SWZ_T(c, t) ((c) ^ (((t) & 7) << 2))

// ======================= attention kernel =======================
// smem words: xsw[64][52]=3328 | qkv[64][148]=9472 (q w0-47, k w48-95, v w96-143)
//   | sc f32 [64][64]=4096 (XOR) | probw[64][36]=2304    total 19200 w = 76800 B
#define XSW_OFF   0
#define QKW_OFF   3328
#define SC_OFF    12800
#define PROBW_OFF 16896
#define ATTN_SMEM_WORDS 19200
#define QP 148

__global__ void __launch_bounds__(256, 2) attn_kernel(
    const float* __restrict__ xin, float* __restrict__ xout,
    const unsigned* __restrict__ wqkv, const float* __restrict__ qkvb,
    const unsigned* __restrict__ wproj, const float* __restrict__ projb,
    const float* __restrict__ rpb,
    const float* __restrict__ g1, const float* __restrict__ bb1,
    int shift)
{
    extern __shared__ float sm[];
    unsigned* xsw   = (unsigned*)sm + XSW_OFF;
    unsigned* qkw   = (unsigned*)sm + QKW_OFF;
    float*    sc    = sm + SC_OFF;
    unsigned* probw = (unsigned*)sm + PROBW_OFF;

    const int tid = threadIdx.x, lane = tid & 31, wid = tid >> 5;
    const int g = lane >> 2, tg = lane & 3;
    const int wm = wid >> 1, wn = wid & 1;
    const int m0 = wm * 16;
    const int l15 = lane & 15, sel4 = (lane >> 4) << 2;

    const int win = blockIdx.x;
    const int b = win >> 10, wi = win & 1023, wh = wi >> 5, ww = wi & 31;

    // ---------- phase 1: LN1 -> xsw (bf16x2) ----------
    {
        int t = tid >> 2, l4 = tid & 3;
        int th = t >> 3, tw = t & 7;
        int h0 = (wh*8 + th + shift) & 255, w0 = (ww*8 + tw + shift) & 255;
        const float* xr = xin + ((size_t)b*65536 + (size_t)h0*256 + w0)*96;
        float v0[12], v1[12], s = 0.f, ss = 0.f;
        #pragma unroll
        for (int jw = 0; jw < 12; jw++) {
            float2 p = *(const float2*)&xr[2*(l4 + 4*jw)];
            v0[jw] = p.x; v1[jw] = p.y;
            s += p.x + p.y; ss += p.x*p.x + p.y*p.y;
        }
        s  += __shfl_xor_sync(0xffffffffu, s, 1);
        s  += __shfl_xor_sync(0xffffffffu, s, 2);
        ss += __shfl_xor_sync(0xffffffffu, ss, 1);
        ss += __shfl_xor_sync(0xffffffffu, ss, 2);
        float mean = s * (1.f/96.f);
        float rstd = rsqrtf(ss * (1.f/96.f) - mean*mean + 1e-5f);
        #pragma unroll
        for (int jw = 0; jw < 12; jw++) {
            int w = l4 + 4*jw;
            int c0 = 2*w;
            float a = (v0[jw]-mean)*rstd*g1[c0]   + bb1[c0];
            float b2 = (v1[jw]-mean)*rstd*g1[c0+1] + bb1[c0+1];
            xsw[t*52 + w] = pack_bf16x2(a, b2);
        }
    }
    __syncthreads();

    // ---------- phase 2: QKV GEMM (bf16); q/k/v -> qkw packed along d ----------
    {
        unsigned Af[6][4];
        #pragma unroll
        for (int kk = 0; kk < 6; kk++)
            ldsm_x4(Af[kk], sptr(&xsw[(m0 + l15)*52 + kk*8 + sel4]));
        for (int s3 = 0; s3 < 3; s3++) {
            float acc[6][4];
            #pragma unroll
            for (int i = 0; i < 6; i++) { acc[i][0]=acc[i][1]=acc[i][2]=acc[i][3]=0.f; }
            #pragma unroll
            for (int kk = 0; kk < 6; kk++) {
                #pragma unroll
                for (int nt = 0; nt < 6; nt++) {
                    int ntg = s3*12 + wn*6 + nt;
                    uint2 bv = *(const uint2*)&wqkv[((ntg*6 + kk)*32 + lane)*2];
                    unsigned bb[2] = { bv.x, bv.y };
                    mma_bf16(acc[nt], Af[kk], bb);
                }
            }
            #pragma unroll
            for (int nt = 0; nt < 6; nt++) {
                #pragma unroll
                for (int i = 0; i < 2; i++) {
                    int ncol = wn*48 + nt*8 + 2*tg;
                    int m = m0 + g + i*8;
                    float a = acc[nt][i*2]   + __ldg(&qkvb[s3*96 + ncol]);
                    float c2 = acc[nt][i*2+1] + __ldg(&qkvb[s3*96 + ncol + 1]);
                    if (s3 == 0) { a *= 0.25f; c2 *= 0.25f; }
                    int w = s3*48 + wn*24 + nt*4 + tg;
                    qkw[m*QP + w] = pack_bf16x2(a, c2);
                }
            }
        }
    }
    __syncthreads();

    // ---------- phase 3: per-head attention (bf16 core) ----------
    for (int h = 0; h < 6; h++) {
        // scores: warp tile [m0,m0+16) x [wn*32,+32)
        {
            unsigned Aq[4];
            ldsm_x4(Aq, sptr(&qkw[(m0 + l15)*QP + h*8 + sel4]));
            float acc[4][4];
            #pragma unroll
            for (int i = 0; i < 4; i++) { acc[i][0]=acc[i][1]=acc[i][2]=acc[i][3]=0.f; }
            #pragma unroll
            for (int nt = 0; nt < 4; nt++) {
                int u0 = wn*32 + nt*8;
                unsigned Bk[2];
                ldsm_x2(Bk, sptr(&qkw[(u0 + (lane & 7))*QP + 48 + h*8 + (((lane>>3)&1)<<2)]));
                mma_bf16(acc[nt], Aq, Bk);
            }
            #pragma unroll
            for (int nt = 0; nt < 4; nt++) {
                #pragma unroll
                for (int i = 0; i < 2; i++) {
                    #pragma unroll
                    for (int j = 0; j < 2; j++) {
                        int t = m0 + g + i*8;
                        int u = wn*32 + nt*8 + 2*tg + j;
                        int ti = t>>3, tj = t&7, ui = u>>3, uj = u&7;
                        float d = acc[nt][i*2+j]
                                + __ldg(&rpb[((ti-ui+7)*15 + (tj-uj+7))*6 + h]);
                        if (shift) {
                            int hrt = wh*8+ti, wrt = ww*8+tj;
                            int hru = wh*8+ui, wru = ww*8+uj;
                            int rt = (hrt<248?0:(hrt<252?1:2))*3 + (wrt<248?0:(wrt<252?1:2));
                            int ru = (hru<248?0:(hru<252?1:2))*3 + (wru<248?0:(wru<252?1:2));
                            if (rt != ru) d -= 100.f;
                        }
                        sc[t*64 + SWZ_T(u, t)] = d;
                    }
                }
            }
        }
        __syncthreads();

        // softmax (f32) -> probw (bf16x2 along u)
        {
            int t = tid >> 2, l4 = tid & 3;
            float e0[8], e1[8];
            float mx = -1e30f;
            #pragma unroll
            for (int jw = 0; jw < 8; jw++) {
                int a = SWZ_T(2*(l4 + 4*jw), t);
                float2 p = *(const float2*)&sc[t*64 + a];
                e0[jw] = p.x; e1[jw] = p.y;
                mx = fmaxf(mx, fmaxf(p.x, p.y));
            }
            mx = fmaxf(mx, __shfl_xor_sync(0xffffffffu, mx, 1));
            mx = fmaxf(mx, __shfl_xor_sync(0xffffffffu, mx, 2));
            float sum = 0.f;
            #pragma unroll
            for (int jw = 0; jw < 8; jw++) {
                e0[jw] = __expf(e0[jw] - mx);
                e1[jw] = __expf(e1[jw] - mx);
                sum += e0[jw] + e1[jw];
            }
            sum += __shfl_xor_sync(0xffffffffu, sum, 1);
            sum += __shfl_xor_sync(0xffffffffu, sum, 2);
            float inv = 1.f / sum;
            #pragma unroll
            for (int jw = 0; jw < 8; jw++)
                probw[t*36 + l4 + 4*jw] = pack_bf16x2(e0[jw]*inv, e1[jw]*inv);
        }
        __syncthreads();

        // P@V (bf16): V B-frags transposed on the fly
        {
            float av[4] = {0.f, 0.f, 0.f, 0.f};
            int dw = 96 + h*8 + wn*4;          // v d-word base for this head/wn
            #pragma unroll
            for (int kk = 0; kk < 4; kk++) {
                unsigned Ap[4];
                ldsm_x4(Ap, sptr(&probw[(m0 + l15)*36 + kk*8 + sel4]));
                unsigned Bv[2];
                ldsm_x2t(Bv, sptr(&qkw[(kk*16 + l15)*QP + dw]));
                mma_bf16(av, Ap, Bv);
            }
            int wv = h*8 + wn*4 + tg;
            xsw[(m0+g)*52   + wv] = pack_bf16x2(av[0], av[1]);
            xsw[(m0+g+8)*52 + wv] = pack_bf16x2(av[2], av[3]);
        }
        __syncthreads();
    }

    // ---------- phase 4: proj (bf16) + residual -> gmem ----------
    {
        unsigned Ac[6][4];
        #pragma unroll
        for (int kk = 0; kk < 6; kk++)
            ldsm_x4(Ac[kk], sptr(&xsw[(m0 + l15)*52 + kk*8 + sel4]));
        float acc[6][4];
        #pragma unroll
        for (int i = 0; i < 6; i++) { acc[i][0]=acc[i][1]=acc[i][2]=acc[i][3]=0.f; }
        #pragma unroll
        for (int kk = 0; kk < 6; kk++) {
            #pragma unroll
            for (int nt = 0; nt < 6; nt++) {
                int ntg = wn*6 + nt;
                uint2 bv = *(const uint2*)&wproj[((ntg*6 + kk)*32 + lane)*2];
                unsigned bb[2] = { bv.x, bv.y };
                mma_bf16(acc[nt], Ac[kk], bb);
            }
        }
        #pragma unroll
        for (int nt = 0; nt < 6; nt++) {
            #pragma unroll
            for (int i = 0; i < 2; i++) {
                int ncol0 = wn*48 + nt*8 + 2*tg;
                int m = m0 + g + i*8;
                int th = m >> 3, tw = m & 7;
                int h0 = (wh*8 + th + shift) & 255;
                int w0 = (ww*8 + tw + shift) & 255;
                size_t row = ((size_t)b*65536 + (size_t)h0*256 + w0)*96;
                float2 rr = *(const float2*)&xin[row + ncol0];
                float2 o;
                o.x = rr.x + acc[nt][i*2]   + __ldg(&projb[ncol0]);
                o.y = rr.y + acc[nt][i*2+1] + __ldg(&projb[ncol0+1]);
                *(float2*)&xout[row + ncol0] = o;
            }
        }
    }
}

// ======================= MLP kernel =======================
#define MLP_SMEM_WORDS (3328 + 3328)

__global__ void __launch_bounds__(256, 2) mlp_kernel(
    const float* __restrict__ xin, float* __restrict__ xout,
    const float* __restrict__ g2, const float* __restrict__ bb2,
    const unsigned* __restrict__ w1p, const float* __restrict__ b1v,
    const unsigned* __restrict__ w2p, const float* __restrict__ b2v)
{
    extern __shared__ float sm[];
    unsigned* xsw = (unsigned*)sm;
    unsigned* ybw = (unsigned*)sm + 3328;

    const int tid = threadIdx.x, lane = tid & 31, wid = tid >> 5;
    const int g = lane >> 2, tg = lane & 3;
    const int wm = wid >> 1, wn = wid & 1;
    const int m0 = wm * 16;
    const int l15 = lane & 15, sel4 = (lane >> 4) << 2;
    const size_t base = (size_t)blockIdx.x * 64 * 96;

    {
        int t = tid >> 2, l4 = tid & 3;
        const float* xr = xin + base + (size_t)t*96;
        float v0[12], v1[12], s = 0.f, ss = 0.f;
        #pragma unroll
        for (int jw = 0; jw < 12; jw++) {
            float2 p = *(const float2*)&xr[2*(l4 + 4*jw)];
            v0[jw] = p.x; v1[jw] = p.y;
            s += p.x + p.y; ss += p.x*p.x + p.y*p.y;
        }
        s  += __shfl_xor_sync(0xffffffffu, s, 1);
        s  += __shfl_xor_sync(0xffffffffu, s, 2);
        ss += __shfl_xor_sync(0xffffffffu, ss, 1);
        ss += __shfl_xor_sync(0xffffffffu, ss, 2);
        float mean = s * (1.f/96.f);
        float rstd = rsqrtf(ss * (1.f/96.f) - mean*mean + 1e-5f);
        #pragma unroll
        for (int jw = 0; jw < 12; jw++) {
            int w = l4 + 4*jw;
            int c0 = 2*w;
            float a = (v0[jw]-mean)*rstd*g2[c0]   + bb2[c0];
            float b2 = (v1[jw]-mean)*rstd*g2[c0+1] + bb2[c0+1];
            xsw[t*52 + w] = pack_bf16x2(a, b2);
        }
    }
    __syncthreads();

    unsigned Af[6][4];
    #pragma unroll
    for (int kk = 0; kk < 6; kk++)
        ldsm_x4(Af[kk], sptr(&xsw[(m0 + l15)*52 + kk*8 + sel4]));

    float acc2[6][4];
    #pragma unroll
    for (int i = 0; i < 6; i++) { acc2[i][0]=acc2[i][1]=acc2[i][2]=acc2[i][3]=0.f; }

    for (int ch = 0; ch < 4; ch++) {
        float acc[6][4];
        #pragma unroll
        for (int i = 0; i < 6; i++) { acc[i][0]=acc[i][1]=acc[i][2]=acc[i][3]=0.f; }
        #pragma unroll
        for (int kk = 0; kk < 6; kk++) {
            #pragma unroll
            for (int nt = 0; nt < 6; nt++) {
                int ntg = ch*12 + wn*6 + nt;
                uint2 bv = *(const uint2*)&w1p[((ntg*6 + kk)*32 + lane)*2];
                unsigned bb[2] = { bv.x, bv.y };
                mma_bf16(acc[nt], Af[kk], bb);
            }
        }
        #pragma unroll
        for (int nt = 0; nt < 6; nt++) {
            int wv = wn*24 + nt*4 + tg;
            #pragma unroll
            for (int i = 0; i < 2; i++) {
                int c0 = wn*48 + nt*8 + 2*tg;
                float a = acc[nt][i*2]   + __ldg(&b1v[ch*96 + c0]);
                float b2 = acc[nt][i*2+1] + __ldg(&b1v[ch*96 + c0 + 1]);
                a = a * normcdff(a);
                b2 = b2 * normcdff(b2);
                ybw[(m0+g+i*8)*52 + wv] = pack_bf16x2(a, b2);
            }
        }
        __syncthreads();
        #pragma unroll
        for (int kk = 0; kk < 6; kk++) {
            unsigned Ay[4];
            ldsm_x4(Ay, sptr(&ybw[(m0 + l15)*52 + kk*8 + sel4]));
            #pragma unroll
            for (int nt = 0; nt < 6; nt++) {
                int ntg = wn*6 + nt;
                int kkg = ch*6 + kk;
                uint2 bv = *(const uint2*)&w2p[((ntg*24 + kkg)*32 + lane)*2];
                unsigned bb[2] = { bv.x, bv.y };
                mma_bf16(acc2[nt], Ay, bb);
            }
        }
        __syncthreads();
    }

    #pragma unroll
    for (int nt = 0; nt < 6; nt++) {
        #pragma unroll
        for (int i = 0; i < 2; i++) {
            int c0 = wn*48 + nt*8 + 2*tg;
            int m = m0 + g + i*8;
            float2 r = *(const float2*)&xin[base + (size_t)m*96 + c0];
            float2 o;
            o.x = r.x + acc2[nt][i*2]   + __ldg(&b2v[c0]);
            o.y = r.y + acc2[nt][i*2+1] + __ldg(&b2v[c0+1]);
            *(float2*)&xout[base + (size_t)m*96 + c0] = o;
        }
    }
}

// ======================= launcher =======================
extern "C" void kernel_launch(void* const* d_in, const int* in_sizes, int n_in,
                              void* d_out, int out_size) {
    const float* x    = (const float*)d_in[0];
    const float* qkvw = (const float*)d_in[1];
    const float* qkvb = (const float*)d_in[2];
    const float* projw= (const float*)d_in[3];
    const float* projb= (const float*)d_in[4];
    const float* rpb  = (const float*)d_in[5];
    const float* n1w  = (const float*)d_in[6];
    const float* n1b  = (const float*)d_in[7];
    const float* n2w  = (const float*)d_in[8];
    const float* n2b  = (const float*)d_in[9];
    const float* f1w  = (const float*)d_in[10];
    const float* f1b  = (const float*)d_in[11];
    const float* f2w  = (const float*)d_in[12];
    const float* f2b  = (const float*)d_in[13];
    float* out = (float*)d_out;

    unsigned* gw = nullptr;  cudaGetSymbolAddress((void**)&gw, g_w);

    pack_all<<<(W_WORDS + 255)/256, 256>>>(qkvw, projw, f1w, f2w, gw);

    const int ATTN_SMEM = ATTN_SMEM_WORDS * 4;   // 76800 B -> 2 CTAs/SM
    const int MLP_SMEM  = MLP_SMEM_WORDS * 4;    // 26624 B
    cudaFuncSetAttribute(attn_kernel, cudaFuncAttributeMaxDynamicSharedMemorySize, ATTN_SMEM);
    cudaFuncSetAttribute(mlp_kernel,  cudaFuncAttributeMaxDynamicSharedMemorySize, MLP_SMEM);

    const int NBLK = 4096;

    attn_kernel<<<NBLK, 256, ATTN_SMEM>>>(x, out,
        gw + OFF_QKV0, qkvb, gw + OFF_PROJ0, projb, rpb, n1w, n1b, 0);
    mlp_kernel<<<NBLK, 256, MLP_SMEM>>>(out, out,
        n2w, n2b, gw + OFF_F1_0, f1b, gw + OFF_F2_0, f2b);

    attn_kernel<<<NBLK, 256, ATTN_SMEM>>>(out, out,
        gw + OFF_QKV1, qkvb + 288, gw + OFF_PROJ1, projb + 96,
        rpb + 225*6, n1w + 96, n1b + 96, 4);
    mlp_kernel<<<NBLK, 256, MLP_SMEM>>>(out, out,
        n2w + 96, n2b + 96, gw + OFF_F1_1, f1b + 384, gw + OFF_F2_1, f2b + 96);
}